// round 5
// baseline (speedup 1.0000x reference)
#include <cuda_runtime.h>
#include <cstdint>

// x:     [16, 64, 64, 128] f32        (32 MB)
// index: same shape, int64 or int32   (64/32 MB), values < 2^31
// out:   [16, 128, 128, 128] f32      (128 MB)
//
// Steady-state graph-replay loop is HBM-traffic bound: 224 MB mandatory app
// traffic per replay. This kernel maximizes DRAM efficiency: 256-bit accesses,
// two widely-separated streams per thread (channel parallelism), all loads
// front-batched, streaming stores.
//
// Exact-coverage trick: each pooled element owns the 4 cells of its 2x2
// output block (bijection), one thread writes all 4 (value where index
// matches, 0 elsewhere). No atomics, no zero pass.
//
// Index dtype detected in-kernel: LE int64 -> 32-bit words 1,3,5,7 are high
// words of elements 0..3 (always 0); int32 -> they are index[1..7 odd] >= 1.

#define PB 16
#define PH 64
#define PW 64
#define PC 128
#define OH 128
#define OW 128
#define N8 (PB * PH * PW * PC / 8)   // 1,048,576 vec8 elements

__device__ __forceinline__ void ldx8(const float* p, float (&v)[8]) {
    asm("ld.global.nc.v8.f32 {%0,%1,%2,%3,%4,%5,%6,%7}, [%8];"
        : "=f"(v[0]), "=f"(v[1]), "=f"(v[2]), "=f"(v[3]),
          "=f"(v[4]), "=f"(v[5]), "=f"(v[6]), "=f"(v[7])
        : "l"(p));
}

__device__ __forceinline__ void ldi8_32(const int* p, int (&v)[8]) {
    asm("ld.global.nc.v8.b32 {%0,%1,%2,%3,%4,%5,%6,%7}, [%8];"
        : "=r"(v[0]), "=r"(v[1]), "=r"(v[2]), "=r"(v[3]),
          "=r"(v[4]), "=r"(v[5]), "=r"(v[6]), "=r"(v[7])
        : "l"(p));
}

__device__ __forceinline__ void ldi4_64(const void* p, long long (&v)[4]) {
    asm("ld.global.nc.v4.u64 {%0,%1,%2,%3}, [%4];"
        : "=l"(v[0]), "=l"(v[1]), "=l"(v[2]), "=l"(v[3])
        : "l"(p));
}

__device__ __forceinline__ void st8_stream(float* p, const float (&v)[8]) {
    asm volatile(
        "st.global.L2::evict_first.v8.f32 [%0], {%1,%2,%3,%4,%5,%6,%7,%8};"
        :: "l"(p),
           "f"(v[0]), "f"(v[1]), "f"(v[2]), "f"(v[3]),
           "f"(v[4]), "f"(v[5]), "f"(v[6]), "f"(v[7])
        : "memory");
}

__device__ __forceinline__ int base_of(int j8) {
    // j8 -> (b, h, w, c/8); PC/8 = 16
    const int cw = j8 & 15;
    int t = j8 >> 4;
    const int w = t & (PW - 1);
    t >>= 6;
    const int h = t & (PH - 1);
    const int b = t >> 6;
    return (((b * OH + 2 * h) * OW) + 2 * w) * PC + 8 * cw;
}

__device__ __forceinline__ void load_idx8(const void* idx_raw, int j8,
                                          bool is64, int (&ix)[8]) {
    if (is64) {
        long long a[4], c[4];
        const char* p = (const char*)idx_raw + (size_t)j8 * 64;
        ldi4_64(p, a);
        ldi4_64(p + 32, c);
        #pragma unroll
        for (int k = 0; k < 4; k++) { ix[k] = (int)a[k]; ix[4 + k] = (int)c[k]; }
    } else {
        ldi8_32((const int*)idx_raw + (size_t)j8 * 8, ix);
    }
}

__device__ __forceinline__ void store_block(float* __restrict__ out,
                                            int base, const float (&v)[8],
                                            const int (&ix)[8]) {
    const int offs[4] = {0, PC, OW * PC, OW * PC + PC};
    #pragma unroll
    for (int k = 0; k < 4; k++) {
        const int o = base + offs[k];         // multiple of 8 -> 32B aligned
        float r[8];
        #pragma unroll
        for (int e = 0; e < 8; e++) r[e] = (ix[e] == o + e) ? v[e] : 0.0f;
        st8_stream(out + o, r);
    }
}

__global__ void __launch_bounds__(512)
unpool_kernel(const float* __restrict__ x,
              const void*  __restrict__ idx_raw,
              float*       __restrict__ out)
{
    // in-kernel dtype detection (broadcast load, uniform branch)
    const uint4* hw = (const uint4*)idx_raw;
    const uint4 w0 = hw[0];
    const uint4 w1 = hw[1];
    const bool is64 = ((w0.y | w0.w | w1.y | w1.w) == 0u);

    const int i  = blockIdx.x * blockDim.x + threadIdx.x;
    const int jA = i;
    const int jB = i + (N8 / 2);   // far stream: different DRAM region

    // front-batch all independent loads (max MLP before first store)
    float vA[8], vB[8];
    ldx8(x + (size_t)jA * 8, vA);
    ldx8(x + (size_t)jB * 8, vB);
    int ixA[8], ixB[8];
    load_idx8(idx_raw, jA, is64, ixA);
    load_idx8(idx_raw, jB, is64, ixB);

    store_block(out, base_of(jA), vA, ixA);
    store_block(out, base_of(jB), vB, ixB);
}

extern "C" void kernel_launch(void* const* d_in, const int* in_sizes, int n_in,
                              void* d_out, int out_size)
{
    const float* x   = (const float*)d_in[0];
    const void*  idx = d_in[1];
    float* out = (float*)d_out;

    const int threads = 512;
    const int blocks  = (N8 / 2) / threads;   // 1024 blocks
    unpool_kernel<<<blocks, threads>>>(x, idx, out);
}

// round 6
// speedup vs baseline: 1.0396x; 1.0396x over previous
#include <cuda_runtime.h>
#include <cstdint>

// x:     [16, 64, 64, 128] f32        (32 MB)   — default-cached loads
// index: same shape, int64 or int32   (64/32 MB) — default-cached loads
// out:   [16, 128, 128, 128] f32      (128 MB)  — st.global.wt (write-through)
//
// Strategy: inputs (96 MB) fit in L2 (126 MB). Output stores use WRITE-THROUGH
// so they do not claim/dirty L2 residency; across graph replays the inputs
// stay L2-resident and steady-state DRAM traffic drops from 224 MB to the
// mandatory 128 MB of output writes. (L2::evict_* hints were proven no-ops
// in R3/R4 — byte-identical timings; .wt has architectural semantics.)
//
// Exact-coverage trick: each pooled element (b,h,w,c) owns the 4 cells of its
// 2x2 output block (bijection), one thread writes all 4 (value where index
// matches, 0 elsewhere). No atomics, no zero pass. Stores are full 32B
// sectors in warp-contiguous 512B runs -> no DRAM read-modify-write.
//
// Index dtype detected in-kernel: LE int64 -> 32-bit words 1,3,5,7 are high
// words of elements 0..3 (always 0, values < 2^31); int32 -> they are
// index[1],[3],[5],[7] which are >= 1. Uniform branch, broadcast load.

#define PB 16
#define PH 64
#define PW 64
#define PC 128
#define OH 128
#define OW 128
#define N8 (PB * PH * PW * PC / 8)   // 1,048,576 vec8 elements

__device__ __forceinline__ void ldx8(const float* p, float (&v)[8]) {
    asm("ld.global.nc.v8.f32 {%0,%1,%2,%3,%4,%5,%6,%7}, [%8];"
        : "=f"(v[0]), "=f"(v[1]), "=f"(v[2]), "=f"(v[3]),
          "=f"(v[4]), "=f"(v[5]), "=f"(v[6]), "=f"(v[7])
        : "l"(p));
}

__device__ __forceinline__ void ldi8_32(const int* p, int (&v)[8]) {
    asm("ld.global.nc.v8.b32 {%0,%1,%2,%3,%4,%5,%6,%7}, [%8];"
        : "=r"(v[0]), "=r"(v[1]), "=r"(v[2]), "=r"(v[3]),
          "=r"(v[4]), "=r"(v[5]), "=r"(v[6]), "=r"(v[7])
        : "l"(p));
}

__device__ __forceinline__ void ldi4_64(const void* p, long long (&v)[4]) {
    asm("ld.global.nc.v4.u64 {%0,%1,%2,%3}, [%4];"
        : "=l"(v[0]), "=l"(v[1]), "=l"(v[2]), "=l"(v[3])
        : "l"(p));
}

// Write-through store: goes to memory without establishing L2 residency.
__device__ __forceinline__ void st8_wt(float* p, const float (&v)[8]) {
    asm volatile(
        "st.global.wt.v8.f32 [%0], {%1,%2,%3,%4,%5,%6,%7,%8};"
        :: "l"(p),
           "f"(v[0]), "f"(v[1]), "f"(v[2]), "f"(v[3]),
           "f"(v[4]), "f"(v[5]), "f"(v[6]), "f"(v[7])
        : "memory");
}

__global__ void __launch_bounds__(256)
unpool_kernel(const float* __restrict__ x,
              const void*  __restrict__ idx_raw,
              float*       __restrict__ out)
{
    // in-kernel dtype detection (broadcast load, uniform branch)
    const uint4* hw = (const uint4*)idx_raw;
    const uint4 w0 = hw[0];
    const uint4 w1 = hw[1];
    const bool is64 = ((w0.y | w0.w | w1.y | w1.w) == 0u);

    const int j8 = blockIdx.x * blockDim.x + threadIdx.x;  // one vec8 per thread
    // j8 -> (b, h, w, c/8); PC/8 = 16
    const int cw = j8 & 15;
    int t = j8 >> 4;
    const int w = t & (PW - 1);
    t >>= 6;
    const int h = t & (PH - 1);
    const int b = t >> 6;
    const int base = (((b * OH + 2 * h) * OW) + 2 * w) * PC + 8 * cw;

    // front-batched independent loads
    float v[8];
    ldx8(x + (size_t)j8 * 8, v);

    int ix[8];
    if (is64) {
        long long a[4], c[4];
        const char* p = (const char*)idx_raw + (size_t)j8 * 64;
        ldi4_64(p, a);
        ldi4_64(p + 32, c);
        #pragma unroll
        for (int k = 0; k < 4; k++) { ix[k] = (int)a[k]; ix[4 + k] = (int)c[k]; }
    } else {
        ldi8_32((const int*)idx_raw + (size_t)j8 * 8, ix);
    }

    // 4 cells of the 2x2 block (all offsets multiples of 8 -> 32B aligned)
    const int offs[4] = {0, PC, OW * PC, OW * PC + PC};
    #pragma unroll
    for (int k = 0; k < 4; k++) {
        const int o = base + offs[k];
        float r[8];
        #pragma unroll
        for (int e = 0; e < 8; e++) r[e] = (ix[e] == o + e) ? v[e] : 0.0f;
        st8_wt(out + o, r);
    }
}

extern "C" void kernel_launch(void* const* d_in, const int* in_sizes, int n_in,
                              void* d_out, int out_size)
{
    const float* x   = (const float*)d_in[0];
    const void*  idx = d_in[1];
    float* out = (float*)d_out;

    const int threads = 256;
    const int blocks  = N8 / threads;        // 4096 blocks
    unpool_kernel<<<blocks, threads>>>(x, idx, out);
}

// round 7
// speedup vs baseline: 1.0462x; 1.0063x over previous
#include <cuda_runtime.h>
#include <cstdint>

// MaxUnpooling2D — roofline-pinned final form.
//
// x:     [16, 64, 64, 128] f32        (32 MB read)
// index: same shape, int64 or int32   (64/32 MB read), values < 2^31
// out:   [16, 128, 128, 128] f32      (128 MB write)
//
// Steady-state graph-replay loop is HBM-bound: 224 MB mandatory traffic per
// replay at ~6.35 TB/s (~80% of spec). Measured invariant across every L2
// policy (evict_first/evict_last both ways, st.wt): hints are inert without
// the (forbidden) persisting-L2 carveout. This kernel is the minimal-traffic,
// maximal-efficiency form:
//   - exact-coverage writes: each pooled element owns the 4 cells of its 2x2
//     output block (index construction is a per-block bijection), so one
//     thread writes all 4 cells (value where index matches, else 0).
//     No atomics, no zero pass, every output byte written exactly once.
//   - 256-bit v8 loads/stores, all loads front-batched (max MLP).
//   - per-CTA streams are fully contiguous in all three buffers.
//
// Index dtype detected in-kernel: LE int64 -> 32-bit words 1,3,5,7 are high
// words of elements 0..3 (always 0, values < 2^31); int32 -> they are
// index[1],[3],[5],[7], each >= 1. Broadcast load, uniform branch.

#define PB 16
#define PH 64
#define PW 64
#define PC 128
#define OH 128
#define OW 128
#define N8 (PB * PH * PW * PC / 8)   // 1,048,576 vec8 elements

__device__ __forceinline__ void ldx8(const float* p, float (&v)[8]) {
    asm("ld.global.nc.v8.f32 {%0,%1,%2,%3,%4,%5,%6,%7}, [%8];"
        : "=f"(v[0]), "=f"(v[1]), "=f"(v[2]), "=f"(v[3]),
          "=f"(v[4]), "=f"(v[5]), "=f"(v[6]), "=f"(v[7])
        : "l"(p));
}

__device__ __forceinline__ void ldi8_32(const int* p, int (&v)[8]) {
    asm("ld.global.nc.v8.b32 {%0,%1,%2,%3,%4,%5,%6,%7}, [%8];"
        : "=r"(v[0]), "=r"(v[1]), "=r"(v[2]), "=r"(v[3]),
          "=r"(v[4]), "=r"(v[5]), "=r"(v[6]), "=r"(v[7])
        : "l"(p));
}

__device__ __forceinline__ void ldi4_64(const void* p, long long (&v)[4]) {
    asm("ld.global.nc.v4.u64 {%0,%1,%2,%3}, [%4];"
        : "=l"(v[0]), "=l"(v[1]), "=l"(v[2]), "=l"(v[3])
        : "l"(p));
}

__device__ __forceinline__ void st8(float* p, const float (&v)[8]) {
    asm volatile(
        "st.global.v8.f32 [%0], {%1,%2,%3,%4,%5,%6,%7,%8};"
        :: "l"(p),
           "f"(v[0]), "f"(v[1]), "f"(v[2]), "f"(v[3]),
           "f"(v[4]), "f"(v[5]), "f"(v[6]), "f"(v[7])
        : "memory");
}

__global__ void __launch_bounds__(128)
unpool_kernel(const float* __restrict__ x,
              const void*  __restrict__ idx_raw,
              float*       __restrict__ out)
{
    // in-kernel dtype detection (broadcast load, uniform branch)
    const uint4* hw = (const uint4*)idx_raw;
    const uint4 w0 = hw[0];
    const uint4 w1 = hw[1];
    const bool is64 = ((w0.y | w0.w | w1.y | w1.w) == 0u);

    const int j8 = blockIdx.x * blockDim.x + threadIdx.x;  // one vec8 per thread
    // j8 -> (b, h, w, c/8); PC/8 = 16
    const int cw = j8 & 15;
    int t = j8 >> 4;
    const int w = t & (PW - 1);
    t >>= 6;
    const int h = t & (PH - 1);
    const int b = t >> 6;
    const int base = (((b * OH + 2 * h) * OW) + 2 * w) * PC + 8 * cw;

    // front-batched independent loads (x: 32B; idx: 64B or 32B)
    float v[8];
    ldx8(x + (size_t)j8 * 8, v);

    int ix[8];
    if (is64) {
        long long a[4], c[4];
        const char* p = (const char*)idx_raw + (size_t)j8 * 64;
        ldi4_64(p, a);
        ldi4_64(p + 32, c);
        #pragma unroll
        for (int k = 0; k < 4; k++) { ix[k] = (int)a[k]; ix[4 + k] = (int)c[k]; }
    } else {
        ldi8_32((const int*)idx_raw + (size_t)j8 * 8, ix);
    }

    // 4 cells of the 2x2 block (all offsets multiples of 8 -> 32B aligned)
    const int offs[4] = {0, PC, OW * PC, OW * PC + PC};
    #pragma unroll
    for (int k = 0; k < 4; k++) {
        const int o = base + offs[k];
        float r[8];
        #pragma unroll
        for (int e = 0; e < 8; e++) r[e] = (ix[e] == o + e) ? v[e] : 0.0f;
        st8(out + o, r);
    }
}

extern "C" void kernel_launch(void* const* d_in, const int* in_sizes, int n_in,
                              void* d_out, int out_size)
{
    const float* x   = (const float*)d_in[0];
    const void*  idx = d_in[1];
    float* out = (float*)d_out;

    const int threads = 128;
    const int blocks  = N8 / threads;        // 8192 blocks
    unpool_kernel<<<blocks, threads>>>(x, idx, out);
}